// round 8
// baseline (speedup 1.0000x reference)
#include <cuda_runtime.h>
#include <cstdint>

#define NF   40
#define ED   128
#define AD   128
#define NP   780     // 40*39/2
#define NPP  784     // 98 n-tiles of 8 pairs
#define NTHR 384     // 12 warps = 3 pair-groups x 4 a-slots
#define NWRP 12
#define XST  132     // padded row stride for x in smem (floats); 528B, 16B-aligned

__device__ __forceinline__ uint32_t tf32_of(float f) {
    uint32_t r;
    asm("cvt.rna.tf32.f32 %0, %1;" : "=r"(r) : "f"(f));
    return r;
}

// D(m16n8) += A(m16k8, tf32, row) * B(k8n8, tf32, col), fp32 accum
__device__ __forceinline__ void mma8(float* d, const uint32_t* a, float b0f, float b1f) {
    uint32_t b0 = __float_as_uint(b0f), b1 = __float_as_uint(b1f);  // raw f32 bits as tf32
    asm volatile(
        "mma.sync.aligned.m16n8k8.row.col.f32.tf32.tf32.f32 "
        "{%0,%1,%2,%3}, {%4,%5,%6,%7}, {%8,%9}, {%0,%1,%2,%3};"
        : "+f"(d[0]), "+f"(d[1]), "+f"(d[2]), "+f"(d[3])
        : "r"(a[0]), "r"(a[1]), "r"(a[2]), "r"(a[3]), "r"(b0), "r"(b1));
}

__global__ void __launch_bounds__(NTHR, 1)
afm_kernel(const float* __restrict__ x,    // [B, F, E]
           const float* __restrict__ ww,   // [A, E]
           const float* __restrict__ wb,   // [A]
           const float* __restrict__ hw,   // [1, A]
           const float* __restrict__ pw,   // [1, E]
           const float* __restrict__ pb,   // [1]
           float* __restrict__ out)        // [B]
{
    __shared__ float   xs[NF * XST];      // ~21.1 KB, row-major padded
    __shared__ float   scs4[4][NPP];      // per-aslot partial scores
    __shared__ float   scs[NPP];
    __shared__ float   dvs[NPP];          // d[p] = hp_p . p_w
    __shared__ float   pws[ED];
    __shared__ uint8_t pis[NPP], pjs[NPP];
    __shared__ float   red[3 * NWRP];

    const int tid  = threadIdx.x;
    const int wid  = tid >> 5, lane = tid & 31;
    const int g     = wid >> 2;       // pair-group 0..2
    const int aslot = wid & 3;        // owns a-rows [aslot*32, +32)
    const int q = lane >> 2, c = lane & 3;
    const int b = blockIdx.x;

    // ---- Stage x (row-major, padded stride) ----
    const float* xg = x + (size_t)b * (NF * ED);
    for (int idx = tid; idx < NF * ED; idx += NTHR)
        xs[(idx >> 7) * XST + (idx & 127)] = xg[idx];
    for (int e = tid; e < ED; e += NTHR) pws[e] = pw[e];

    // ---- Pair index tables (triu i<j, i-major) ----
    for (int p = tid; p < NPP; p += NTHR) {
        if (p < NP) {
            int i = 0, rem = p;
            while (rem >= NF - 1 - i) { rem -= NF - 1 - i; i++; }
            pis[p] = (uint8_t)i; pjs[p] = (uint8_t)(i + 1 + rem);
        } else { pis[p] = 0; pjs[p] = 1; }
    }

    // ---- W fragments (register-stationary), e-permuted to the segment map:
    //      step s=2u+t: logical k=c   <-> e = 16u + 4c + 2t
    //                   logical k=c+4 <-> e + 1
    const int A0 = aslot * 32;
    uint32_t wA[2][16][4];
    #pragma unroll
    for (int mt = 0; mt < 2; mt++) {
        #pragma unroll
        for (int s = 0; s < 16; s++) {
            int e  = 16 * (s >> 1) + 4 * c + 2 * (s & 1);
            int r0 = (A0 + mt * 16 + q) * ED + e;
            int r1 = r0 + 8 * ED;
            float2 w0 = *(const float2*)&ww[r0];
            float2 w1 = *(const float2*)&ww[r1];
            wA[mt][s][0] = tf32_of(w0.x);
            wA[mt][s][1] = tf32_of(w1.x);
            wA[mt][s][2] = tf32_of(w0.y);
            wA[mt][s][3] = tf32_of(w1.y);
        }
    }

    __syncthreads();

    // ---- Main loop: n-tiles of 8 pairs; group g covers [g*33, min(g*33+33, 98)) ----
    const int nt0 = g * 33;
    const int nt1 = (g == 2) ? 98 : nt0 + 33;
    const bool do_d = (aslot == 0);   // this warp also accumulates d[p] = hp . pw

    for (int nt = nt0; nt < nt1; nt++) {
        const int p = nt * 8 + q;                 // this quad's pair (B col)
        const float* xi = &xs[(int)pis[p] * XST + 4 * c];
        const float* xj = &xs[(int)pjs[p] * XST + 4 * c];

        // 4 independent accumulator chains: (m-tile 0/1) x (even/odd u)
        float accA0[4] = {0.f, 0.f, 0.f, 0.f};
        float accB0[4] = {0.f, 0.f, 0.f, 0.f};
        float accA1[4] = {0.f, 0.f, 0.f, 0.f};
        float accB1[4] = {0.f, 0.f, 0.f, 0.f};
        float dacc = 0.f;

        // software-pipelined segment loads (1 step ahead)
        float4 vi = *(const float4*)&xi[0];
        float4 vj = *(const float4*)&xj[0];
        #pragma unroll
        for (int u = 0; u < 8; u++) {
            float4 cvi = vi, cvj = vj;
            if (u < 7) {
                vi = *(const float4*)&xi[16 * (u + 1)];
                vj = *(const float4*)&xj[16 * (u + 1)];
            }
            float p0 = cvi.x * cvj.x, p1 = cvi.y * cvj.y;
            float p2 = cvi.z * cvj.z, p3 = cvi.w * cvj.w;
            float* d0 = (u & 1) ? accB0 : accA0;
            float* d1 = (u & 1) ? accB1 : accA1;
            mma8(d0, wA[0][2 * u],     p0, p1);
            mma8(d1, wA[1][2 * u],     p0, p1);
            mma8(d0, wA[0][2 * u + 1], p2, p3);
            mma8(d1, wA[1][2 * u + 1], p2, p3);
            if (do_d) {
                float4 pw4 = *(const float4*)&pws[16 * u + 4 * c];
                dacc = fmaf(p0, pw4.x, fmaf(p1, pw4.y, fmaf(p2, pw4.z, fmaf(p3, pw4.w, dacc))));
            }
        }
        if (do_d) {
            dacc += __shfl_xor_sync(0xffffffffu, dacc, 1);
            dacc += __shfl_xor_sync(0xffffffffu, dacc, 2);
            if (c == 0 && p < NP) dvs[p] = dacc;
        }

        float acc0[4], acc1[4];
        #pragma unroll
        for (int r = 0; r < 4; r++) {
            acc0[r] = accA0[r] + accB0[r];
            acc1[r] = accA1[r] + accB1[r];
        }

        // Fused epilogue: partial score = sum over this warp's 32 a of h*relu(.+wb)
        float s0 = 0.f, s1 = 0.f;
        #pragma unroll
        for (int u = 0; u < 4; u++) {
            int a = A0 + u * 8 + q;
            float wbu = __ldg(&wb[a]);
            float hu  = __ldg(&hw[a]);
            float au0 = (u < 2) ? acc0[2 * u]     : acc1[2 * (u - 2)];
            float au1 = (u < 2) ? acc0[2 * u + 1] : acc1[2 * (u - 2) + 1];
            s0 += fmaxf(au0 + wbu, 0.f) * hu;
            s1 += fmaxf(au1 + wbu, 0.f) * hu;
        }
        #pragma unroll
        for (int o = 4; o <= 16; o <<= 1) {
            s0 += __shfl_xor_sync(0xffffffffu, s0, o);
            s1 += __shfl_xor_sync(0xffffffffu, s1, o);
        }
        if (lane < 4) {
            scs4[aslot][nt * 8 + 2 * lane]     = s0;
            scs4[aslot][nt * 8 + 2 * lane + 1] = s1;
        }
    }
    __syncthreads();

    for (int p = tid; p < NP; p += NTHR)
        scs[p] = scs4[0][p] + scs4[1][p] + scs4[2][p] + scs4[3][p];
    __syncthreads();

    // ---- Softmax over pairs + weighted sum (h_b softmax-invariant, dropped) ----
    float lmax = -3.4e38f;
    for (int p = tid; p < NP; p += NTHR) lmax = fmaxf(lmax, scs[p]);
    #pragma unroll
    for (int o = 16; o; o >>= 1) lmax = fmaxf(lmax, __shfl_xor_sync(0xffffffffu, lmax, o));
    if (lane == 0) red[wid] = lmax;
    __syncthreads();
    float m = red[0];
    #pragma unroll
    for (int w = 1; w < NWRP; w++) m = fmaxf(m, red[w]);

    float se = 0.f, sd = 0.f;
    for (int p = tid; p < NP; p += NTHR) {
        float e = __expf(scs[p] - m);
        se += e;
        sd = fmaf(e, dvs[p], sd);
    }
    #pragma unroll
    for (int o = 16; o; o >>= 1) {
        se += __shfl_xor_sync(0xffffffffu, se, o);
        sd += __shfl_xor_sync(0xffffffffu, sd, o);
    }
    if (lane == 0) { red[NWRP + wid] = se; red[2 * NWRP + wid] = sd; }
    __syncthreads();
    if (tid == 0) {
        float S = 0.f, D = 0.f;
        #pragma unroll
        for (int w = 0; w < NWRP; w++) { S += red[NWRP + w]; D += red[2 * NWRP + w]; }
        out[b] = D / S + pb[0];
    }
}

extern "C" void kernel_launch(void* const* d_in, const int* in_sizes, int n_in,
                              void* d_out, int out_size) {
    const float* x  = (const float*)d_in[0];
    const float* ww = (const float*)d_in[1];
    const float* wb = (const float*)d_in[2];
    const float* hw = (const float*)d_in[3];
    // d_in[4] = attn_h_b: uniform shift on scores, softmax-invariant -> unused
    const float* pw = (const float*)d_in[5];
    const float* pb = (const float*)d_in[6];
    float* out = (float*)d_out;

    int B = in_sizes[0] / (NF * ED);
    afm_kernel<<<B, NTHR>>>(x, ww, wb, hw, pw, pb, out);
}

// round 9
// speedup vs baseline: 1.3921x; 1.3921x over previous
#include <cuda_runtime.h>
#include <cstdint>

#define NF   40
#define ED   128
#define AD   128
#define NP   780     // 40*39/2
#define NPP  784     // 98 n-tiles of 8 pairs
#define NTHR 256     // 8 warps = 2 pair-groups x 4 a-slots
#define NWRP 8
#define XST  132     // padded row stride for x in smem (floats); 528B, 16B-aligned

__device__ __forceinline__ uint32_t tf32_of(float f) {
    uint32_t r;
    asm("cvt.rna.tf32.f32 %0, %1;" : "=r"(r) : "f"(f));
    return r;
}

// D(m16n8) += A(m16k8, tf32, row) * B(k8n8, tf32, col), fp32 accum
__device__ __forceinline__ void mma8(float* d, const uint32_t* a, float b0f, float b1f) {
    uint32_t b0 = __float_as_uint(b0f), b1 = __float_as_uint(b1f);  // raw f32 bits as tf32
    asm volatile(
        "mma.sync.aligned.m16n8k8.row.col.f32.tf32.tf32.f32 "
        "{%0,%1,%2,%3}, {%4,%5,%6,%7}, {%8,%9}, {%0,%1,%2,%3};"
        : "+f"(d[0]), "+f"(d[1]), "+f"(d[2]), "+f"(d[3])
        : "r"(a[0]), "r"(a[1]), "r"(a[2]), "r"(a[3]), "r"(b0), "r"(b1));
}

__global__ void __launch_bounds__(NTHR, 1)
afm_kernel(const float* __restrict__ x,    // [B, F, E]
           const float* __restrict__ ww,   // [A, E]
           const float* __restrict__ wb,   // [A]
           const float* __restrict__ hw,   // [1, A]
           const float* __restrict__ pw,   // [1, E]
           const float* __restrict__ pb,   // [1]
           float* __restrict__ out)        // [B]
{
    __shared__ float   xs[NF * XST];      // ~21.1 KB, row-major padded
    __shared__ float   scs4[4][NPP];      // per-aslot partial scores
    __shared__ float   scs[NPP];
    __shared__ float   dvs[NPP];          // d[p] = hp_p . p_w
    __shared__ float   pws[ED];
    __shared__ float2  swh[AD];           // (wb[a], hw[a])
    __shared__ uint8_t pis[NPP], pjs[NPP];
    __shared__ float   red[3 * NWRP];

    const int tid  = threadIdx.x;
    const int wid  = tid >> 5, lane = tid & 31;
    const int g     = wid >> 2;       // pair-group 0..1
    const int aslot = wid & 3;        // owns a-rows [aslot*32, +32)
    const int q = lane >> 2, c = lane & 3;
    const int b = blockIdx.x;

    // ---- Stage x (row-major, padded stride) ----
    const float* xg = x + (size_t)b * (NF * ED);
    for (int idx = tid; idx < NF * ED; idx += NTHR)
        xs[(idx >> 7) * XST + (idx & 127)] = xg[idx];
    for (int e = tid; e < ED; e += NTHR) pws[e] = pw[e];
    for (int a = tid; a < AD; a += NTHR) swh[a] = make_float2(wb[a], hw[a]);

    // ---- Pair index tables (triu i<j, i-major) ----
    for (int p = tid; p < NPP; p += NTHR) {
        if (p < NP) {
            int i = 0, rem = p;
            while (rem >= NF - 1 - i) { rem -= NF - 1 - i; i++; }
            pis[p] = (uint8_t)i; pjs[p] = (uint8_t)(i + 1 + rem);
        } else { pis[p] = 0; pjs[p] = 1; }
    }

    // ---- W fragments (register-stationary), e-permuted to the segment map:
    //      step s=2u+t: logical k=c   <-> e = 16u + 4c + 2t
    //                   logical k=c+4 <-> e + 1
    const int A0 = aslot * 32;
    uint32_t wA[2][16][4];
    #pragma unroll
    for (int mt = 0; mt < 2; mt++) {
        #pragma unroll
        for (int s = 0; s < 16; s++) {
            int e  = 16 * (s >> 1) + 4 * c + 2 * (s & 1);
            int r0 = (A0 + mt * 16 + q) * ED + e;
            int r1 = r0 + 8 * ED;
            float2 w0 = *(const float2*)&ww[r0];
            float2 w1 = *(const float2*)&ww[r1];
            wA[mt][s][0] = tf32_of(w0.x);
            wA[mt][s][1] = tf32_of(w1.x);
            wA[mt][s][2] = tf32_of(w0.y);
            wA[mt][s][3] = tf32_of(w1.y);
        }
    }

    __syncthreads();

    // ---- Main loop: n-tiles of 8 pairs; group g covers [g*49, g*49+49) ----
    const int nt0 = g * 49;
    const int nt1 = nt0 + 49;

    for (int nt = nt0; nt < nt1; nt++) {
        const int p = nt * 8 + q;                 // this quad's pair (B col)
        const float* xi = &xs[(int)pis[p] * XST + 4 * c];
        const float* xj = &xs[(int)pjs[p] * XST + 4 * c];
        const bool do_d = (aslot == (nt & 3));    // round-robin d-duty

        // 4 independent accumulator chains: (m-tile 0/1) x (even/odd u)
        float accA0[4] = {0.f, 0.f, 0.f, 0.f};
        float accB0[4] = {0.f, 0.f, 0.f, 0.f};
        float accA1[4] = {0.f, 0.f, 0.f, 0.f};
        float accB1[4] = {0.f, 0.f, 0.f, 0.f};
        float dacc = 0.f;

        // software-pipelined segment loads (1 step ahead)
        float4 vi = *(const float4*)&xi[0];
        float4 vj = *(const float4*)&xj[0];
        #pragma unroll
        for (int u = 0; u < 8; u++) {
            float4 cvi = vi, cvj = vj;
            if (u < 7) {
                vi = *(const float4*)&xi[16 * (u + 1)];
                vj = *(const float4*)&xj[16 * (u + 1)];
            }
            float p0 = cvi.x * cvj.x, p1 = cvi.y * cvj.y;
            float p2 = cvi.z * cvj.z, p3 = cvi.w * cvj.w;
            float* d0 = (u & 1) ? accB0 : accA0;
            float* d1 = (u & 1) ? accB1 : accA1;
            mma8(d0, wA[0][2 * u],     p0, p1);
            mma8(d1, wA[1][2 * u],     p0, p1);
            mma8(d0, wA[0][2 * u + 1], p2, p3);
            mma8(d1, wA[1][2 * u + 1], p2, p3);
            if (do_d) {
                float4 pw4 = *(const float4*)&pws[16 * u + 4 * c];
                dacc = fmaf(p0, pw4.x, fmaf(p1, pw4.y, fmaf(p2, pw4.z, fmaf(p3, pw4.w, dacc))));
            }
        }
        if (do_d) {
            dacc += __shfl_xor_sync(0xffffffffu, dacc, 1);
            dacc += __shfl_xor_sync(0xffffffffu, dacc, 2);
            if (c == 0 && p < NP) dvs[p] = dacc;
        }

        float acc0[4], acc1[4];
        #pragma unroll
        for (int r = 0; r < 4; r++) {
            acc0[r] = accA0[r] + accB0[r];
            acc1[r] = accA1[r] + accB1[r];
        }

        // Fused epilogue: partial score = sum over this warp's 32 a of h*relu(.+wb)
        float s0 = 0.f, s1 = 0.f;
        #pragma unroll
        for (int u = 0; u < 4; u++) {
            float2 wh = swh[A0 + u * 8 + q];
            float au0 = (u < 2) ? acc0[2 * u]     : acc1[2 * (u - 2)];
            float au1 = (u < 2) ? acc0[2 * u + 1] : acc1[2 * (u - 2) + 1];
            s0 += fmaxf(au0 + wh.x, 0.f) * wh.y;
            s1 += fmaxf(au1 + wh.x, 0.f) * wh.y;
        }
        #pragma unroll
        for (int o = 4; o <= 16; o <<= 1) {
            s0 += __shfl_xor_sync(0xffffffffu, s0, o);
            s1 += __shfl_xor_sync(0xffffffffu, s1, o);
        }
        if (lane < 4) {
            scs4[aslot][nt * 8 + 2 * lane]     = s0;
            scs4[aslot][nt * 8 + 2 * lane + 1] = s1;
        }
    }
    __syncthreads();

    for (int p = tid; p < NP; p += NTHR)
        scs[p] = scs4[0][p] + scs4[1][p] + scs4[2][p] + scs4[3][p];
    __syncthreads();

    // ---- Softmax over pairs + weighted sum (h_b softmax-invariant, dropped) ----
    float lmax = -3.4e38f;
    for (int p = tid; p < NP; p += NTHR) lmax = fmaxf(lmax, scs[p]);
    #pragma unroll
    for (int o = 16; o; o >>= 1) lmax = fmaxf(lmax, __shfl_xor_sync(0xffffffffu, lmax, o));
    if (lane == 0) red[wid] = lmax;
    __syncthreads();
    float m = red[0];
    #pragma unroll
    for (int w = 1; w < NWRP; w++) m = fmaxf(m, red[w]);

    float se = 0.f, sd = 0.f;
    for (int p = tid; p < NP; p += NTHR) {
        float e = __expf(scs[p] - m);
        se += e;
        sd = fmaf(e, dvs[p], sd);
    }
    #pragma unroll
    for (int o = 16; o; o >>= 1) {
        se += __shfl_xor_sync(0xffffffffu, se, o);
        sd += __shfl_xor_sync(0xffffffffu, sd, o);
    }
    if (lane == 0) { red[NWRP + wid] = se; red[2 * NWRP + wid] = sd; }
    __syncthreads();
    if (tid == 0) {
        float S = 0.f, D = 0.f;
        #pragma unroll
        for (int w = 0; w < NWRP; w++) { S += red[NWRP + w]; D += red[2 * NWRP + w]; }
        out[b] = D / S + pb[0];
    }
}

extern "C" void kernel_launch(void* const* d_in, const int* in_sizes, int n_in,
                              void* d_out, int out_size) {
    const float* x  = (const float*)d_in[0];
    const float* ww = (const float*)d_in[1];
    const float* wb = (const float*)d_in[2];
    const float* hw = (const float*)d_in[3];
    // d_in[4] = attn_h_b: uniform shift on scores, softmax-invariant -> unused
    const float* pw = (const float*)d_in[5];
    const float* pb = (const float*)d_in[6];
    float* out = (float*)d_out;

    int B = in_sizes[0] / (NF * ED);
    afm_kernel<<<B, NTHR>>>(x, ww, wb, hw, pw, pb, out);
}

// round 10
// speedup vs baseline: 1.5869x; 1.1399x over previous
#include <cuda_runtime.h>
#include <cuda_fp16.h>
#include <cstdint>

#define NF   40
#define ED   128
#define AD   128
#define NP   780     // 40*39/2
#define NPP  784     // 98 n-tiles of 8 pairs
#define NTHR 384     // 12 warps = 3 pair-groups x 4 a-slots
#define NWRP 12
#define XST  132     // padded row stride for x in smem (floats); 528B, 16B-aligned

__device__ __forceinline__ uint32_t h2pack(float lo, float hi) {
    __half2 h = __floats2half2_rn(lo, hi);   // .x = lo
    return *(uint32_t*)&h;
}

// D(m16n8) += A(m16k16, f16, row) * B(k16n8, f16, col), fp32 accum
__device__ __forceinline__ void mma16(float* d, const uint32_t* a, uint32_t b0, uint32_t b1) {
    asm volatile(
        "mma.sync.aligned.m16n8k16.row.col.f32.f16.f16.f32 "
        "{%0,%1,%2,%3}, {%4,%5,%6,%7}, {%8,%9}, {%0,%1,%2,%3};"
        : "+f"(d[0]), "+f"(d[1]), "+f"(d[2]), "+f"(d[3])
        : "r"(a[0]), "r"(a[1]), "r"(a[2]), "r"(a[3]), "r"(b0), "r"(b1));
}

__global__ void __launch_bounds__(NTHR, 1)
afm_kernel(const float* __restrict__ x,    // [B, F, E]
           const float* __restrict__ ww,   // [A, E]
           const float* __restrict__ wb,   // [A]
           const float* __restrict__ hw,   // [1, A]
           const float* __restrict__ pw,   // [1, E]
           const float* __restrict__ pb,   // [1]
           float* __restrict__ out)        // [B]
{
    __shared__ float   xs[NF * XST];      // ~21.1 KB, row-major padded
    __shared__ float   scs4[4][NPP];      // per-aslot partial scores
    __shared__ float   scs[NPP];
    __shared__ float   dvs[NPP];          // d[p] = hp_p . p_w
    __shared__ float   pws[ED];
    __shared__ float2  swh[AD];           // (wb[a], hw[a])
    __shared__ uint8_t pis[NPP], pjs[NPP];
    __shared__ float   red[3 * NWRP];

    const int tid  = threadIdx.x;
    const int wid  = tid >> 5, lane = tid & 31;
    const int g     = wid >> 2;       // pair-group 0..2
    const int aslot = wid & 3;        // owns a-rows [aslot*32, +32)
    const int q = lane >> 2, c = lane & 3;
    const int b = blockIdx.x;

    // ---- Stage x (row-major, padded stride) ----
    const float* xg = x + (size_t)b * (NF * ED);
    for (int idx = tid; idx < NF * ED; idx += NTHR)
        xs[(idx >> 7) * XST + (idx & 127)] = xg[idx];
    for (int e = tid; e < ED; e += NTHR) pws[e] = pw[e];
    for (int a = tid; a < AD; a += NTHR) swh[a] = make_float2(wb[a], hw[a]);

    // ---- Pair index tables (triu i<j, i-major) ----
    for (int p = tid; p < NPP; p += NTHR) {
        if (p < NP) {
            int i = 0, rem = p;
            while (rem >= NF - 1 - i) { rem -= NF - 1 - i; i++; }
            pis[p] = (uint8_t)i; pjs[p] = (uint8_t)(i + 1 + rem);
        } else { pis[p] = 0; pjs[p] = 1; }
    }

    // ---- W fragments (register-stationary, fp16-packed), e-permuted:
    //      k16-step s: logical k {2c,2c+1,2c+8,2c+9} <-> e = 16s+4c + {0,1,2,3}
    const int A0 = aslot * 32;
    uint32_t wA[2][8][4];
    #pragma unroll
    for (int mt = 0; mt < 2; mt++) {
        #pragma unroll
        for (int s = 0; s < 8; s++) {
            int e0 = 16 * s + 4 * c;
            int r0 = (A0 + mt * 16 + q) * ED + e0;
            int r1 = r0 + 8 * ED;
            float4 w0 = *(const float4*)&ww[r0];
            float4 w1 = *(const float4*)&ww[r1];
            wA[mt][s][0] = h2pack(w0.x, w0.y);   // A[q][k=2c], [k=2c+1]
            wA[mt][s][1] = h2pack(w1.x, w1.y);   // A[q+8][...]
            wA[mt][s][2] = h2pack(w0.z, w0.w);   // A[q][k=2c+8], [k=2c+9]
            wA[mt][s][3] = h2pack(w1.z, w1.w);   // A[q+8][...]
        }
    }

    __syncthreads();

    // ---- Main loop: n-tiles of 8 pairs; group g covers [g*33, min(g*33+33, 98)) ----
    const int nt0 = g * 33;
    const int nt1 = (g == 2) ? 98 : nt0 + 33;

    for (int nt = nt0; nt < nt1; nt++) {
        const int p = nt * 8 + q;                 // this quad's pair (B col)
        const float* xi = &xs[(int)pis[p] * XST + 4 * c];
        const float* xj = &xs[(int)pjs[p] * XST + 4 * c];
        const bool do_d = (aslot == (nt & 3));    // round-robin d-duty

        // 4 independent accumulator chains: (m-tile 0/1) x (even/odd u)
        float accA0[4] = {0.f, 0.f, 0.f, 0.f};
        float accB0[4] = {0.f, 0.f, 0.f, 0.f};
        float accA1[4] = {0.f, 0.f, 0.f, 0.f};
        float accB1[4] = {0.f, 0.f, 0.f, 0.f};
        float dacc = 0.f;

        // software-pipelined segment loads (1 step ahead)
        float4 vi = *(const float4*)&xi[0];
        float4 vj = *(const float4*)&xj[0];
        #pragma unroll
        for (int u = 0; u < 8; u++) {
            float4 cvi = vi, cvj = vj;
            if (u < 7) {
                vi = *(const float4*)&xi[16 * (u + 1)];
                vj = *(const float4*)&xj[16 * (u + 1)];
            }
            float p0 = cvi.x * cvj.x, p1 = cvi.y * cvj.y;
            float p2 = cvi.z * cvj.z, p3 = cvi.w * cvj.w;
            uint32_t b0 = h2pack(p0, p1);         // k = 2c, 2c+1
            uint32_t b1 = h2pack(p2, p3);         // k = 2c+8, 2c+9
            float* d0 = (u & 1) ? accB0 : accA0;
            float* d1 = (u & 1) ? accB1 : accA1;
            mma16(d0, wA[0][u], b0, b1);
            mma16(d1, wA[1][u], b0, b1);
            if (do_d) {
                float4 pw4 = *(const float4*)&pws[16 * u + 4 * c];
                dacc = fmaf(p0, pw4.x, fmaf(p1, pw4.y, fmaf(p2, pw4.z, fmaf(p3, pw4.w, dacc))));
            }
        }
        if (do_d) {
            dacc += __shfl_xor_sync(0xffffffffu, dacc, 1);
            dacc += __shfl_xor_sync(0xffffffffu, dacc, 2);
            if (c == 0 && p < NP) dvs[p] = dacc;
        }

        float acc0[4], acc1[4];
        #pragma unroll
        for (int r = 0; r < 4; r++) {
            acc0[r] = accA0[r] + accB0[r];
            acc1[r] = accA1[r] + accB1[r];
        }

        // Fused epilogue: partial score = sum over this warp's 32 a of h*relu(.+wb)
        float s0 = 0.f, s1 = 0.f;
        #pragma unroll
        for (int u = 0; u < 4; u++) {
            float2 wh = swh[A0 + u * 8 + q];
            float au0 = (u < 2) ? acc0[2 * u]     : acc1[2 * (u - 2)];
            float au1 = (u < 2) ? acc0[2 * u + 1] : acc1[2 * (u - 2) + 1];
            s0 += fmaxf(au0 + wh.x, 0.f) * wh.y;
            s1 += fmaxf(au1 + wh.x, 0.f) * wh.y;
        }
        #pragma unroll
        for (int o = 4; o <= 16; o <<= 1) {
            s0 += __shfl_xor_sync(0xffffffffu, s0, o);
            s1 += __shfl_xor_sync(0xffffffffu, s1, o);
        }
        if (lane < 4) {
            scs4[aslot][nt * 8 + 2 * lane]     = s0;
            scs4[aslot][nt * 8 + 2 * lane + 1] = s1;
        }
    }
    __syncthreads();

    for (int p = tid; p < NP; p += NTHR)
        scs[p] = scs4[0][p] + scs4[1][p] + scs4[2][p] + scs4[3][p];
    __syncthreads();

    // ---- Softmax over pairs + weighted sum (h_b softmax-invariant, dropped) ----
    float lmax = -3.4e38f;
    for (int p = tid; p < NP; p += NTHR) lmax = fmaxf(lmax, scs[p]);
    #pragma unroll
    for (int o = 16; o; o >>= 1) lmax = fmaxf(lmax, __shfl_xor_sync(0xffffffffu, lmax, o));
    if (lane == 0) red[wid] = lmax;
    __syncthreads();
    float m = red[0];
    #pragma unroll
    for (int w = 1; w < NWRP; w++) m = fmaxf(m, red[w]);

    float se = 0.f, sd = 0.f;
    for (int p = tid; p < NP; p += NTHR) {
        float e = __expf(scs[p] - m);
        se += e;
        sd = fmaf(e, dvs[p], sd);
    }
    #pragma unroll
    for (int o = 16; o; o >>= 1) {
        se += __shfl_xor_sync(0xffffffffu, se, o);
        sd += __shfl_xor_sync(0xffffffffu, sd, o);
    }
    if (lane == 0) { red[NWRP + wid] = se; red[2 * NWRP + wid] = sd; }
    __syncthreads();
    if (tid == 0) {
        float S = 0.f, D = 0.f;
        #pragma unroll
        for (int w = 0; w < NWRP; w++) { S += red[NWRP + w]; D += red[2 * NWRP + w]; }
        out[b] = D / S + pb[0];
    }
}

extern "C" void kernel_launch(void* const* d_in, const int* in_sizes, int n_in,
                              void* d_out, int out_size) {
    const float* x  = (const float*)d_in[0];
    const float* ww = (const float*)d_in[1];
    const float* wb = (const float*)d_in[2];
    const float* hw = (const float*)d_in[3];
    // d_in[4] = attn_h_b: uniform shift on scores, softmax-invariant -> unused
    const float* pw = (const float*)d_in[5];
    const float* pb = (const float*)d_in[6];
    float* out = (float*)d_out;

    int B = in_sizes[0] / (NF * ED);
    afm_kernel<<<B, NTHR>>>(x, ww, wb, hw, pw, pb, out);
}